// round 3
// baseline (speedup 1.0000x reference)
#include <cuda_runtime.h>

#define Bb 16
#define Tt 160
#define Uu 80
#define U1 81
#define Vv 512
#define NDIAG 240     // diagonals d = t+u in [0,239]
#define DSTR 88       // diagonal row stride (floats), 16B aligned
#define L2E 1.4426950408889634f
#define LN2 0.6931471805599453f
#define DPB 4         // dp blocks (4 warps = 4 batches each)
#define RPB (Tt*U1)   // rows per batch = 12960
#define REG1 3240     // rows with d in [0,79]   (triangle)
#define REG2 9720     // + rows with d in [80,159] (81 each)

// Scratch (allocation-free rule). Tables are log2-domain, anti-diagonal layout.
__device__ float g_blank[Bb*NDIAG*DSTR];
__device__ float g_lab  [Bb*NDIAG*DSTR];
__device__ int   g_cnt  [Bb*NDIAG];   // rows completed per (b,d); self-resetting
__device__ float g_ll   [Bb];
__device__ int   g_done;              // dp-warp completion counter; self-resetting

// ---------------------------------------------------------------------------
__device__ __forceinline__ float exp_fast(float x) {   // FMA-only, |x| small
    const float MAGIC = 12582912.0f;                    // 1.5 * 2^23
    float z = fmaf(x, L2E, MAGIC);
    float w = z - MAGIC;
    float f = fmaf(x, L2E, -w);
    float p =               9.6181291076e-3f;
    p = fmaf(p, f, 5.5504108664e-2f);
    p = fmaf(p, f, 2.4022650696e-1f);
    p = fmaf(p, f, 6.9314718056e-1f);
    p = fmaf(p, f, 1.0f);
    return __int_as_float(__float_as_int(p) + (__float_as_int(z) << 23));
}

__device__ __forceinline__ int tri_inv(int x) {   // largest j with j(j+1)/2 <= x
    int j = (int)((sqrtf((float)(8*x + 1)) - 1.0f) * 0.5f);
    while ((j + 1) * (j + 2) / 2 <= x) ++j;
    while (j * (j + 1) / 2 > x) --j;
    return j;
}

__device__ __forceinline__ int Kof(int d) {       // rows on diagonal d
    return min(d, 80) - max(0, d - 159) + 1;
}

__device__ __forceinline__ int ld_acq(const int* p) {
    int v;
    asm volatile("ld.acquire.gpu.global.u32 %0, [%1];" : "=r"(v) : "l"(p));
    return v;
}
__device__ __forceinline__ void inc_release(int* p) {
    asm volatile("red.release.gpu.global.add.u32 [%0], 1;" :: "l"(p) : "memory");
}

// log2-domain logaddexp with validity guards; NaN from (-inf)-(-inf) clamped.
__device__ __forceinline__ float dstep(bool cb, bool cl, float vs, float vl,
                                       float bl, float la) {
    float tb = cb ? vs + bl : -INFINITY;
    float tl = cl ? vl + la : -INFINITY;
    float mx = fmaxf(tb, tl);
    float mn = fminf(tb, tl);
    float d  = fmaxf(mn - mx, -126.0f);
    float e;  asm("ex2.approx.f32 %0, %1;" : "=f"(e) : "f"(d));
    float l;  asm("lg2.approx.f32 %0, %1;" : "=f"(l) : "f"(1.0f + e));
    return mx + l;
}

// ---------------------------------------------------------------------------
__global__ void __launch_bounds__(256) fused_kernel(const float* __restrict__ logits,
                                                    const int* __restrict__ targets,
                                                    const int* __restrict__ tl_arr,
                                                    const int* __restrict__ ul_arr,
                                                    float* __restrict__ out) {
    int lane = threadIdx.x & 31;

    if (blockIdx.x >= DPB) {
        // ================= LSE producer role =================
        int gw = (blockIdx.x - DPB) * 8 + (threadIdx.x >> 5);
        int b = gw & 15;          // batch-minor so each diagonal set completes together
        int r = gw >> 4;          // row index ordered by ascending diagonal d
        int d, u;
        if (r < REG1)      { d = tri_inv(r); u = r - d * (d + 1) / 2; }
        else if (r < REG2) { int q = r - REG1; int dq = q / 81; d = 80 + dq; u = q - dq * 81; }
        else {               int r2 = (RPB - 1) - r; int j = tri_inv(r2);
                             int off = r2 - j * (j + 1) / 2;
                             d = 239 - j; u = (d - 159) + j - off; }
        int t = d - u;
        int row = (b * Tt + t) * U1 + u;

        const float4* p = reinterpret_cast<const float4*>(logits) + (size_t)row * (Vv / 4);
        float4 a  = __ldcs(p + lane);
        float4 b4 = __ldcs(p + lane + 32);
        float4 c  = __ldcs(p + lane + 64);
        float4 dd = __ldcs(p + lane + 96);

        float s0 = (exp_fast(a.x)  + exp_fast(a.y))  + (exp_fast(a.z)  + exp_fast(a.w));
        float s1 = (exp_fast(b4.x) + exp_fast(b4.y)) + (exp_fast(b4.z) + exp_fast(b4.w));
        float s2 = (exp_fast(c.x)  + exp_fast(c.y))  + (exp_fast(c.z)  + exp_fast(c.w));
        float s3 = (exp_fast(dd.x) + exp_fast(dd.y)) + (exp_fast(dd.z) + exp_fast(dd.w));
        float s  = (s0 + s1) + (s2 + s3);
#pragma unroll
        for (int o = 16; o; o >>= 1) s += __shfl_xor_sync(0xffffffffu, s, o);

        float blank_logit = __shfl_sync(0xffffffffu, dd.w, 31);  // element 511

        if (lane == 0) {
            float lse2;
            asm("lg2.approx.f32 %0, %1;" : "=f"(lse2) : "f"(s));
            int tgt = targets[b * Uu + min(u, Uu - 1)];
            float lab_logit = __ldg(logits + (size_t)row * Vv + tgt);
            int o = (b * NDIAG + d) * DSTR + u;
            g_blank[o] = fmaf(blank_logit, L2E, -lse2);
            g_lab[o]   = fmaf(lab_logit,   L2E, -lse2);
            inc_release(&g_cnt[b * NDIAG + d]);    // publish row
        }
        return;
    }

    // ================= DP consumer role (blocks 0..3, warps 0..3) =================
    int wid = threadIdx.x >> 5;
    if (wid >= 4) return;
    int b = blockIdx.x * 4 + wid;

    int tl = tl_arr[b], ul = ul_arr[b];
    int dtar = tl - 1 + ul;
    int u0 = lane * 4;
    int uoff = min(u0, 84);                   // clamp high lanes in-bounds
    const float* bbl = g_blank + b * NDIAG * DSTR;
    const float* bla = g_lab   + b * NDIAG * DSTR;
    int* cnt = g_cnt + b * NDIAG;

    bool is_owner = (lane == (ul >> 2));
    int  sel = ul & 3;
    float saved = (dtar == 0 && lane == 0) ? 0.0f : -INFINITY;

    float v0 = -INFINITY, v1 = -INFINITY, v2 = -INFINITY, v3 = -INFINITY;
    if (lane == 0) v0 = 0.0f;                 // alpha[0][0] (log2 domain)

    for (int c = 0; c < 15; ++c) {
        // Wait for source diagonals [16c, 16c+15] of this batch to be complete.
        int dd   = 16 * c + lane;
        int need = (lane < 16) ? Kof(dd) : 0;
        for (;;) {
            int have = (lane < 16) ? ld_acq(&cnt[dd]) : 0x7fffffff;
            if (__all_sync(0xffffffffu, have >= need)) break;
            __nanosleep(200);
        }

        int sd0 = 16 * c;
        float4 cbl = __ldcg(reinterpret_cast<const float4*>(bbl + sd0 * DSTR + uoff));
        float4 cla = __ldcg(reinterpret_cast<const float4*>(bla + sd0 * DSTR + uoff));
#pragma unroll
        for (int k = 0; k < 16; ++k) {
            int d = sd0 + k + 1;              // target diagonal (d=240 iter is harmless)
            float4 nbl = cbl, nla = cla;
            if (k < 15) {                      // depth-1 prefetch within chunk
                nbl = __ldcg(reinterpret_cast<const float4*>(bbl + (sd0 + k + 1) * DSTR + uoff));
                nla = __ldcg(reinterpret_cast<const float4*>(bla + (sd0 + k + 1) * DSTR + uoff));
            }
            float vleft = __shfl_up_sync(0xffffffffu, v3,    1);
            float lleft = __shfl_up_sync(0xffffffffu, cla.w, 1);
            if (lane == 0) vleft = -INFINITY;

            float nv0 = dstep(d > u0,     d >= u0,     v0, vleft, cbl.x, lleft);
            float nv1 = dstep(d > u0 + 1, d >= u0 + 1, v1, v0,    cbl.y, cla.x);
            float nv2 = dstep(d > u0 + 2, d >= u0 + 2, v2, v1,    cbl.z, cla.y);
            float nv3 = dstep(d > u0 + 3, d >= u0 + 3, v3, v2,    cbl.w, cla.z);

            if (d == dtar && is_owner)         // branch-free-ish target capture
                saved = sel == 0 ? nv0 : sel == 1 ? nv1 : sel == 2 ? nv2 : nv3;

            v0 = nv0; v1 = nv1; v2 = nv2; v3 = nv3;
            cbl = nbl; cla = nla;
        }
    }

    // Reset this batch's counters for the next graph replay (all waits done).
    for (int i = lane; i < NDIAG; i += 32) cnt[i] = 0;

    if (is_owner) {
        float blank2 = __ldcg(bbl + dtar * DSTR + ul);
        g_ll[b] = saved + blank2;             // log2-domain log-likelihood
        __threadfence();
        int prev = atomicAdd(&g_done, 1);
        if (prev == Bb - 1) {                 // last finisher reduces deterministically
            __threadfence();
            float sll = 0.0f;
#pragma unroll
            for (int i = 0; i < Bb; ++i) sll += __ldcg(&g_ll[i]);
            out[0] = sll * (-LN2 / (float)Bb);
            g_done = 0;                        // reset for next replay
        }
    }
}

extern "C" void kernel_launch(void* const* d_in, const int* in_sizes, int n_in,
                              void* d_out, int out_size) {
    const float* logits  = (const float*)d_in[0];
    const int*   targets = (const int*)d_in[1];
    const int*   tl      = (const int*)d_in[2];
    const int*   ul      = (const int*)d_in[3];

    const int ROWS = Bb * Tt * U1;                 // 207360 rows, 8 warps/block
    fused_kernel<<<DPB + ROWS / 8, 256>>>(logits, targets, tl, ul, (float*)d_out);
}

// round 4
// speedup vs baseline: 1.0145x; 1.0145x over previous
#include <cuda_runtime.h>

#define Bb 16
#define Tt 160
#define Uu 80
#define U1 81
#define Vv 512
#define NDIAG 240     // diagonals d = t+u in [0,239]
#define DSTR 88       // diagonal row stride (floats), 16B aligned
#define L2E 1.4426950408889634f
#define LN2 0.6931471805599453f
#define DPB 4         // dp blocks, 4 warps (=4 batches) each
#define NEG_INF __int_as_float(0xFF800000)

// Scratch (allocation-free rule). Tables: log2-domain, anti-diagonal layout.
__device__ float g_blank[Bb*NDIAG*DSTR];
__device__ float g_lab  [Bb*NDIAG*DSTR];
__device__ int   g_cnt  [Bb*Tt];      // rows completed per (b,t); self-resetting
__device__ float g_ll   [Bb];
__device__ int   g_done;              // dp completion counter; self-resetting

// ---------------------------------------------------------------------------
__device__ __forceinline__ float exp_fast(float x) {   // FMA-only
    const float MAGIC = 12582912.0f;                    // 1.5 * 2^23
    float z = fmaf(x, L2E, MAGIC);
    float w = z - MAGIC;
    float f = fmaf(x, L2E, -w);
    float p =               9.6181291076e-3f;
    p = fmaf(p, f, 5.5504108664e-2f);
    p = fmaf(p, f, 2.4022650696e-1f);
    p = fmaf(p, f, 6.9314718056e-1f);
    p = fmaf(p, f, 1.0f);
    return __int_as_float(__float_as_int(p) + (__float_as_int(z) << 23));
}

__device__ __forceinline__ int ld_acq(const int* p) {
    int v;
    asm volatile("ld.acquire.gpu.global.u32 %0, [%1];" : "=r"(v) : "l"(p));
    return v;
}
__device__ __forceinline__ void inc_release(int* p) {
    asm volatile("red.release.gpu.global.add.u32 [%0], 1;" :: "l"(p) : "memory");
}

// Guard-free log2-domain logaddexp of (vs+bl, vl+la); -inf pads do the masking.
// Both -inf -> nd = NaN -> clamped -126 -> mx(-inf) + tiny = -inf.
__device__ __forceinline__ float dstep(float vs, float vl, float bl, float la) {
    float x = vs + bl;
    float y = vl + la;
    float mx = fmaxf(x, y);
    float nd = fminf(x - y, y - x);     // -|x-y|
    nd = fmaxf(nd, -126.0f);
    float e;  asm("ex2.approx.f32 %0, %1;" : "=f"(e) : "f"(nd));
    float l;  asm("lg2.approx.f32 %0, %1;" : "=f"(l) : "f"(1.0f + e));
    return mx + l;
}

// ---------------------------------------------------------------------------
__global__ void __launch_bounds__(256) fused_kernel(const float* __restrict__ logits,
                                                    const int* __restrict__ targets,
                                                    const int* __restrict__ tl_arr,
                                                    const int* __restrict__ ul_arr,
                                                    float* __restrict__ out) {
    int lane = threadIdx.x & 31;

    if (blockIdx.x >= DPB) {
        // ================= LSE producer: gw -> (t, b, u), u innermost ========
        int gw = (blockIdx.x - DPB) * 8 + (threadIdx.x >> 5);
        int t   = gw / (Bb * U1);
        int rem = gw - t * (Bb * U1);
        int b   = rem / U1;
        int u   = rem - b * U1;
        int row = (b * Tt + t) * U1 + u;     // contiguous with gw (u innermost)

        const float4* p = reinterpret_cast<const float4*>(logits) + (size_t)row * (Vv / 4);
        float4 a  = __ldcs(p + lane);
        float4 b4 = __ldcs(p + lane + 32);
        float4 c  = __ldcs(p + lane + 64);
        float4 dd = __ldcs(p + lane + 96);

        float s0 = (exp_fast(a.x)  + exp_fast(a.y))  + (exp_fast(a.z)  + exp_fast(a.w));
        float s1 = (exp_fast(b4.x) + exp_fast(b4.y)) + (exp_fast(b4.z) + exp_fast(b4.w));
        float s2 = (exp_fast(c.x)  + exp_fast(c.y))  + (exp_fast(c.z)  + exp_fast(c.w));
        float s3 = (exp_fast(dd.x) + exp_fast(dd.y)) + (exp_fast(dd.z) + exp_fast(dd.w));
        float s  = (s0 + s1) + (s2 + s3);
#pragma unroll
        for (int o = 16; o; o >>= 1) s += __shfl_xor_sync(0xffffffffu, s, o);

        float blank_logit = __shfl_sync(0xffffffffu, dd.w, 31);  // element 511

        if (lane == 0) {
            float lse2;
            asm("lg2.approx.f32 %0, %1;" : "=f"(lse2) : "f"(s));
            int tgt = targets[b * Uu + min(u, Uu - 1)];
            float lab_logit = __ldg(logits + (size_t)row * Vv + tgt);
            int o = (b * NDIAG + (t + u)) * DSTR + u;
            g_blank[o] = fmaf(blank_logit, L2E, -lse2);
            g_lab[o]   = fmaf(lab_logit,   L2E, -lse2);
            inc_release(&g_cnt[b * Tt + t]);       // publish row of slice (b,t)
        }
        return;
    }

    // ================= DP consumer: blocks 0..3, warp w = batch ==============
    int wid = threadIdx.x >> 5;
    if (wid >= 4) return;
    int b = blockIdx.x * 4 + wid;

    float* bbl = g_blank + b * NDIAG * DSTR;
    float* bla = g_lab   + b * NDIAG * DSTR;
    int*   cnt = g_cnt   + b * Tt;

    // Pad-fill: -inf everywhere lse won't write (disjoint -> race-free).
    for (int idx = lane; idx < NDIAG * DSTR; idx += 32) {
        int d = idx / DSTR;
        int u = idx - d * DSTR;
        int lo = max(0, d - 159), hi = min(d, 80);
        if (u < lo || u > hi) { bbl[idx] = NEG_INF; bla[idx] = NEG_INF; }
    }

    int tl = tl_arr[b], ul = ul_arr[b];
    int dtar = tl - 1 + ul;
    int u0   = lane * 4;
    int uoff = min(u0, 84);
    bool is_owner = (lane == (ul >> 2));
    int  sel = ul & 3;
    float saved = (dtar == 0 && lane == 0) ? 0.0f : NEG_INF;

    float v0 = NEG_INF, v1 = NEG_INF, v2 = NEG_INF, v3 = NEG_INF;
    if (lane == 0) v0 = 0.0f;                 // alpha[0][0] (log2 domain)

    for (int c = 0; c < 15; ++c) {
        // Wait for t-slices [16c, 16c+15] (clamped) of this batch: 81 rows each.
        int s_t  = min(16 * c + lane, Tt - 1);
        for (;;) {
            int have = (lane < 16) ? ld_acq(&cnt[s_t]) : 0x7fffffff;
            if (__all_sync(0xffffffffu, have >= U1)) break;
            __nanosleep(200);
        }

        int sd0 = 16 * c;
        float4 cbl = __ldcg(reinterpret_cast<const float4*>(bbl + sd0 * DSTR + uoff));
        float4 cla = __ldcg(reinterpret_cast<const float4*>(bla + sd0 * DSTR + uoff));
#pragma unroll
        for (int k = 0; k < 16; ++k) {
            int d = sd0 + k + 1;               // target diagonal
            int dpre = min(d, NDIAG - 1);      // branch-free depth-1 prefetch
            float4 nbl = __ldcg(reinterpret_cast<const float4*>(bbl + dpre * DSTR + uoff));
            float4 nla = __ldcg(reinterpret_cast<const float4*>(bla + dpre * DSTR + uoff));

            float vleft = __shfl_up_sync(0xffffffffu, v3,    1);
            float lleft = __shfl_up_sync(0xffffffffu, cla.w, 1);
            if (lane == 0) vleft = NEG_INF;    // u=0 has no left neighbor

            float nv0 = dstep(v0, vleft, cbl.x, lleft);
            float nv1 = dstep(v1, v0,    cbl.y, cla.x);
            float nv2 = dstep(v2, v1,    cbl.z, cla.y);
            float nv3 = dstep(v3, v2,    cbl.w, cla.z);

            if (d == dtar && is_owner)
                saved = sel == 0 ? nv0 : sel == 1 ? nv1 : sel == 2 ? nv2 : nv3;

            v0 = nv0; v1 = nv1; v2 = nv2; v3 = nv3;
            cbl = nbl; cla = nla;
        }
    }

    // All waits passed -> all increments for this batch observed; reset slices.
    for (int i = lane; i < Tt; i += 32) cnt[i] = 0;

    if (is_owner) {
        float blank2 = __ldcg(bbl + dtar * DSTR + ul);
        g_ll[b] = saved + blank2;              // log2-domain log-likelihood
        __threadfence();
        int prev = atomicAdd(&g_done, 1);
        if (prev == Bb - 1) {                  // deterministic single-writer reduce
            __threadfence();
            float sll = 0.0f;
#pragma unroll
            for (int i = 0; i < Bb; ++i) sll += __ldcg(&g_ll[i]);
            out[0] = sll * (-LN2 / (float)Bb);
            g_done = 0;                        // reset for next graph replay
        }
    }
}

extern "C" void kernel_launch(void* const* d_in, const int* in_sizes, int n_in,
                              void* d_out, int out_size) {
    const float* logits  = (const float*)d_in[0];
    const int*   targets = (const int*)d_in[1];
    const int*   tl      = (const int*)d_in[2];
    const int*   ul      = (const int*)d_in[3];

    const int ROWS = Bb * Tt * U1;                 // 207360 rows, 8 warps/block
    fused_kernel<<<DPB + ROWS / 8, 256>>>(logits, targets, tl, ul, (float*)d_out);
}

// round 5
// speedup vs baseline: 1.7887x; 1.7631x over previous
#include <cuda_runtime.h>

#define Bb 16
#define Tt 160
#define Uu 80
#define U1 81
#define Vv 512
#define NDIAG 240     // diagonals d = t+u in [0,239]
#define DSTR 88       // diagonal row stride (floats), 16B aligned
#define L2E 1.4426950408889634f
#define LN2 0.6931471805599453f
#define NEG_INF __int_as_float(0xFF800000)

// Scratch (allocation-free rule). Tables: log2-domain, anti-diagonal layout.
// Cells outside the valid region (t>=tl[b] or u>ul[b]) are never written and
// never flow into the target's dependency closure (garbage flows right/down).
__device__ float g_blank[Bb*NDIAG*DSTR];
__device__ float g_lab  [Bb*NDIAG*DSTR];
__device__ float g_ll   [Bb];
__device__ int   g_done;              // dp completion counter; self-resetting

// ---------------------------------------------------------------------------
__device__ __forceinline__ float exp_fast(float x) {   // FMA-only
    const float MAGIC = 12582912.0f;                    // 1.5 * 2^23
    float z = fmaf(x, L2E, MAGIC);
    float w = z - MAGIC;
    float f = fmaf(x, L2E, -w);
    float p =               9.6181291076e-3f;
    p = fmaf(p, f, 5.5504108664e-2f);
    p = fmaf(p, f, 2.4022650696e-1f);
    p = fmaf(p, f, 6.9314718056e-1f);
    p = fmaf(p, f, 1.0f);
    return __int_as_float(__float_as_int(p) + (__float_as_int(z) << 23));
}

// Guard-free log2-domain logaddexp of (vs+bl, vl+la). -inf pads mask edges.
// NaN-safe: both -inf -> nd=NaN -> fmaxf(NaN,-126)=-126 -> mx(-inf)+eps=-inf.
// One -inf / one NaN operand -> returns the finite one (fmaxf drops NaN).
__device__ __forceinline__ float dstep(float vs, float vl, float bl, float la) {
    float x = vs + bl;
    float y = vl + la;
    float mx = fmaxf(x, y);
    float nd = fminf(x - y, y - x);     // -|x-y|
    nd = fmaxf(nd, -126.0f);
    float e;  asm("ex2.approx.f32 %0, %1;" : "=f"(e) : "f"(nd));
    float l;  asm("lg2.approx.f32 %0, %1;" : "=f"(l) : "f"(1.0f + e));
    return mx + l;
}

// ---------------------------------------------------------------------------
// Kernel 1: per-row logsumexp over V=512, skipping rows outside the valid
// region (43% of traffic on average). One warp per row, 16 floats/lane.
// ---------------------------------------------------------------------------
__global__ void __launch_bounds__(256) lse_kernel(const float* __restrict__ logits,
                                                  const int* __restrict__ targets,
                                                  const int* __restrict__ tl_arr,
                                                  const int* __restrict__ ul_arr) {
    int gw   = (blockIdx.x * 256 + threadIdx.x) >> 5;  // row id
    int lane = threadIdx.x & 31;

    int u  = gw % U1;
    int bt = gw / U1;
    int t  = bt % Tt;
    int b  = bt / Tt;
    if (t >= __ldg(tl_arr + b) || u > __ldg(ul_arr + b)) return;  // dead row

    const float4* p = reinterpret_cast<const float4*>(logits) + (size_t)gw * (Vv / 4);
    float4 a  = __ldcs(p + lane);
    float4 b4 = __ldcs(p + lane + 32);
    float4 c  = __ldcs(p + lane + 64);
    float4 dd = __ldcs(p + lane + 96);

    float s0 = (exp_fast(a.x)  + exp_fast(a.y))  + (exp_fast(a.z)  + exp_fast(a.w));
    float s1 = (exp_fast(b4.x) + exp_fast(b4.y)) + (exp_fast(b4.z) + exp_fast(b4.w));
    float s2 = (exp_fast(c.x)  + exp_fast(c.y))  + (exp_fast(c.z)  + exp_fast(c.w));
    float s3 = (exp_fast(dd.x) + exp_fast(dd.y)) + (exp_fast(dd.z) + exp_fast(dd.w));
    float s  = (s0 + s1) + (s2 + s3);
#pragma unroll
    for (int o = 16; o; o >>= 1) s += __shfl_xor_sync(0xffffffffu, s, o);

    float blank_logit = __shfl_sync(0xffffffffu, dd.w, 31);  // element 511

    if (lane == 0) {
        float lse2;
        asm("lg2.approx.f32 %0, %1;" : "=f"(lse2) : "f"(s));
        int tgt = targets[b * Uu + min(u, Uu - 1)];
        float lab_logit = __ldg(logits + (size_t)gw * Vv + tgt);
        int o = (b * NDIAG + (t + u)) * DSTR + u;
        g_blank[o] = fmaf(blank_logit, L2E, -lse2);
        g_lab[o]   = fmaf(lab_logit,   L2E, -lse2);
    }
}

// ---------------------------------------------------------------------------
// Kernel 2: alpha DP, one block per batch. 256 threads preload rows [0,dtar]
// into smem and -inf-fill the pads; warp 0 runs the wavefront with 4 u-cells
// per lane in registers, depth-1 LDS prefetch, predicated target capture.
// ---------------------------------------------------------------------------
__global__ void __launch_bounds__(256) dp_kernel(const int* __restrict__ tl_arr,
                                                 const int* __restrict__ ul_arr,
                                                 float* __restrict__ out) {
    extern __shared__ float sm[];
    float* s_bl = sm;                    // NDIAG*DSTR
    float* s_la = sm + NDIAG * DSTR;
    int b = blockIdx.x;

    int tl = __ldg(tl_arr + b), ul = __ldg(ul_arr + b);
    int dtar = tl - 1 + ul;

    // Preload rows [0, dtar] of both tables (full 88-wide rows).
    int n4 = (dtar + 1) * (DSTR / 4);
    const float4* gb = reinterpret_cast<const float4*>(g_blank + b * NDIAG * DSTR);
    const float4* gl = reinterpret_cast<const float4*>(g_lab   + b * NDIAG * DSTR);
    for (int i = threadIdx.x; i < n4; i += 256) {
        reinterpret_cast<float4*>(s_bl)[i] = __ldcg(gb + i);
        reinterpret_cast<float4*>(s_la)[i] = __ldcg(gl + i);
    }
    __syncthreads();

    // -inf pads: cells outside the lattice domain of each diagonal row.
    for (int idx = threadIdx.x; idx < (dtar + 1) * DSTR; idx += 256) {
        int d = idx / DSTR;
        int u = idx - d * DSTR;
        int lo = max(0, d - 159), hi = min(d, 80);
        if (u < lo || u > hi) { s_bl[idx] = NEG_INF; s_la[idx] = NEG_INF; }
    }
    __syncthreads();
    if (threadIdx.x >= 32) return;

    int lane = threadIdx.x;
    int u0   = lane * 4;
    int uoff = min(u0, 84);
    bool l0  = (lane == 0);
    bool is_owner = (lane == (ul >> 2));
    int  sel = ul & 3;
    float saved = (dtar == 0 && l0) ? 0.0f : NEG_INF;

    float v0 = NEG_INF, v1 = NEG_INF, v2 = NEG_INF, v3 = NEG_INF;
    if (l0) v0 = 0.0f;                   // alpha[0][0] (log2 domain)

    float4 cbl = *reinterpret_cast<const float4*>(s_bl + uoff);  // row 0
    float4 cla = *reinterpret_cast<const float4*>(s_la + uoff);
    const float* pbl = s_bl + DSTR + uoff;
    const float* pla = s_la + DSTR + uoff;

    for (int d = 1; d <= dtar; ++d) {
        float4 nbl = *reinterpret_cast<const float4*>(pbl);  // prefetch row d
        float4 nla = *reinterpret_cast<const float4*>(pla);
        pbl += DSTR; pla += DSTR;

        float vleft = __shfl_up_sync(0xffffffffu, v3,    1);
        float lleft = __shfl_up_sync(0xffffffffu, cla.w, 1);
        vleft = l0 ? NEG_INF : vleft;     // u=0 has no left neighbor

        float nv0 = dstep(v0, vleft, cbl.x, lleft);
        float nv1 = dstep(v1, v0,    cbl.y, cla.x);
        float nv2 = dstep(v2, v1,    cbl.z, cla.y);
        float nv3 = dstep(v3, v2,    cbl.w, cla.z);

        if (d == dtar && is_owner)        // predicated capture (uniform d)
            saved = sel == 0 ? nv0 : sel == 1 ? nv1 : sel == 2 ? nv2 : nv3;

        v0 = nv0; v1 = nv1; v2 = nv2; v3 = nv3;
        cbl = nbl; cla = nla;
    }
    // After the loop, cbl holds row dtar for this lane's columns.

    if (is_owner) {
        float blank2 = sel == 0 ? cbl.x : sel == 1 ? cbl.y : sel == 2 ? cbl.z : cbl.w;
        g_ll[b] = saved + blank2;         // log2-domain log-likelihood
        __threadfence();
        int prev = atomicAdd(&g_done, 1);
        if (prev == Bb - 1) {             // deterministic single-writer reduce
            __threadfence();
            float sll = 0.0f;
#pragma unroll
            for (int i = 0; i < Bb; ++i) sll += __ldcg(&g_ll[i]);
            out[0] = sll * (-LN2 / (float)Bb);
            g_done = 0;                    // reset for next graph replay
        }
    }
}

extern "C" void kernel_launch(void* const* d_in, const int* in_sizes, int n_in,
                              void* d_out, int out_size) {
    const float* logits  = (const float*)d_in[0];
    const int*   targets = (const int*)d_in[1];
    const int*   tl      = (const int*)d_in[2];
    const int*   ul      = (const int*)d_in[3];

    const int ROWS = Bb * Tt * U1;                 // 207360 rows, 8 warps/block
    lse_kernel<<<ROWS / 8, 256>>>(logits, targets, tl, ul);

    size_t smem = 2 * NDIAG * DSTR * sizeof(float);  // 168,960 B
    cudaFuncSetAttribute(dp_kernel, cudaFuncAttributeMaxDynamicSharedMemorySize, (int)smem);
    dp_kernel<<<Bb, 256, smem>>>(tl, ul, (float*)d_out);
}

// round 6
// speedup vs baseline: 1.8987x; 1.0615x over previous
#include <cuda_runtime.h>

#define Bb 16
#define Tt 160
#define Uu 80
#define U1 81
#define Vv 512
#define NDIAG 240     // diagonals d = t+u in [0,239]
#define DSTR 88       // diagonal row stride (floats), 16B aligned
#define L2E 1.4426950408889634f
#define LN2 0.6931471805599453f
#define NEG_INF __int_as_float(0xFF800000)

// Scratch (allocation-free rule). Tables: log2-domain, anti-diagonal layout.
// Cells outside the valid region (t>=tl[b] or u>ul[b]) are never written;
// device globals are zero-initialized, so such cells hold finite 0.0 forever.
__device__ float g_blank[Bb*NDIAG*DSTR];
__device__ float g_lab  [Bb*NDIAG*DSTR];
__device__ float g_ll   [Bb];
__device__ int   g_done;              // dp completion counter; self-resetting

// ---------------------------------------------------------------------------
__device__ __forceinline__ float exp_fast(float x) {   // FMA-only
    const float MAGIC = 12582912.0f;                    // 1.5 * 2^23
    float z = fmaf(x, L2E, MAGIC);
    float w = z - MAGIC;
    float f = fmaf(x, L2E, -w);
    float p =               9.6181291076e-3f;
    p = fmaf(p, f, 5.5504108664e-2f);
    p = fmaf(p, f, 2.4022650696e-1f);
    p = fmaf(p, f, 6.9314718056e-1f);
    p = fmaf(p, f, 1.0f);
    return __int_as_float(__float_as_int(p) + (__float_as_int(z) << 23));
}

// log2-domain logaddexp of (vs+bl, vl+la). No NaN ever escapes: the only NaN
// source is (-inf)-(-inf), clamped to -126 immediately (inputs never +inf/NaN).
__device__ __forceinline__ float dstep(float vs, float vl, float bl, float la) {
    float x = vs + bl;
    float y = vl + la;
    float mx = fmaxf(x, y);
    float mn = fminf(x, y);
    float nd = fmaxf(mn - mx, -126.0f);
    float e;  asm("ex2.approx.f32 %0, %1;" : "=f"(e) : "f"(nd));
    float l;  asm("lg2.approx.f32 %0, %1;" : "=f"(l) : "f"(1.0f + e));
    return mx + l;
}

// ---------------------------------------------------------------------------
// Kernel 1: per-row logsumexp over V=512, skipping dead rows (~43%).
// ---------------------------------------------------------------------------
__global__ void __launch_bounds__(256) lse_kernel(const float* __restrict__ logits,
                                                  const int* __restrict__ targets,
                                                  const int* __restrict__ tl_arr,
                                                  const int* __restrict__ ul_arr) {
    int gw   = (blockIdx.x * 256 + threadIdx.x) >> 5;  // row id
    int lane = threadIdx.x & 31;

    int u  = gw % U1;
    int bt = gw / U1;
    int t  = bt % Tt;
    int b  = bt / Tt;
    if (t >= __ldg(tl_arr + b) || u > __ldg(ul_arr + b)) return;  // dead row

    const float4* p = reinterpret_cast<const float4*>(logits) + (size_t)gw * (Vv / 4);
    float4 a  = __ldcs(p + lane);
    float4 b4 = __ldcs(p + lane + 32);
    float4 c  = __ldcs(p + lane + 64);
    float4 dd = __ldcs(p + lane + 96);

    float s0 = (exp_fast(a.x)  + exp_fast(a.y))  + (exp_fast(a.z)  + exp_fast(a.w));
    float s1 = (exp_fast(b4.x) + exp_fast(b4.y)) + (exp_fast(b4.z) + exp_fast(b4.w));
    float s2 = (exp_fast(c.x)  + exp_fast(c.y))  + (exp_fast(c.z)  + exp_fast(c.w));
    float s3 = (exp_fast(dd.x) + exp_fast(dd.y)) + (exp_fast(dd.z) + exp_fast(dd.w));
    float s  = (s0 + s1) + (s2 + s3);
#pragma unroll
    for (int o = 16; o; o >>= 1) s += __shfl_xor_sync(0xffffffffu, s, o);

    float blank_logit = __shfl_sync(0xffffffffu, dd.w, 31);  // element 511

    if (lane == 0) {
        float lse2;
        asm("lg2.approx.f32 %0, %1;" : "=f"(lse2) : "f"(s));
        int tgt = targets[b * Uu + min(u, Uu - 1)];
        float lab_logit = __ldg(logits + (size_t)gw * Vv + tgt);
        int o = (b * NDIAG + (t + u)) * DSTR + u;
        g_blank[o] = fmaf(blank_logit, L2E, -lse2);
        g_lab[o]   = fmaf(lab_logit,   L2E, -lse2);
    }
}

// ---------------------------------------------------------------------------
// Kernel 2: meet-in-the-middle DP. One block (128 thr) per batch.
//   warp 0: forward alpha up to cut diagonal dm   (dm iterations)
//   warp 1: backward beta down to dm              (dtar-dm iterations)
//   combine: log_like = LSE_u(alpha[dm][u] + beta[dm][u]) over valid u.
// ---------------------------------------------------------------------------
__global__ void __launch_bounds__(128) dp_kernel(const int* __restrict__ tl_arr,
                                                 const int* __restrict__ ul_arr,
                                                 float* __restrict__ out) {
    extern __shared__ float sm[];
    float* s_bl  = sm;
    float* s_la  = sm + NDIAG * DSTR;
    float* s_cmb = sm + 2 * NDIAG * DSTR;  // 88 floats: beta on the cut
    int b = blockIdx.x;

    int tl = __ldg(tl_arr + b), ul = __ldg(ul_arr + b);
    int dtar = tl - 1 + ul;
    int dm   = dtar >> 1;

    // Preload rows [0, dtar] of both tables.
    int n4 = (dtar + 1) * (DSTR / 4);
    const float4* gb = reinterpret_cast<const float4*>(g_blank + b * NDIAG * DSTR);
    const float4* gl = reinterpret_cast<const float4*>(g_lab   + b * NDIAG * DSTR);
    for (int i = threadIdx.x; i < n4; i += 128) {
        reinterpret_cast<float4*>(s_bl)[i] = __ldcg(gb + i);
        reinterpret_cast<float4*>(s_la)[i] = __ldcg(gl + i);
    }
    __syncthreads();
    // -inf pads: cells outside the lattice domain of each diagonal row.
    for (int idx = threadIdx.x; idx < (dtar + 1) * DSTR; idx += 128) {
        int d = idx / DSTR;
        int u = idx - d * DSTR;
        int lo = max(0, d - 159), hi = min(d, 80);
        if (u < lo || u > hi) { s_bl[idx] = NEG_INF; s_la[idx] = NEG_INF; }
    }
    __syncthreads();

    int wid  = threadIdx.x >> 5;
    int lane = threadIdx.x & 31;
    if (wid >= 2) return;
    int u0   = lane * 4;
    int uoff = min(u0, 84);

    if (wid == 1) {
        // ---------------- BACKWARD beta: diag dtar-1 down to dm -------------
        float w0 = NEG_INF, w1 = NEG_INF, w2 = NEG_INF, w3 = NEG_INF;
        float corner = s_bl[dtar * DSTR + ul];     // beta[tl-1][ul] = blank there
        if (lane == (ul >> 2)) {
            int sel = ul & 3;
            if      (sel == 0) w0 = corner;
            else if (sel == 1) w1 = corner;
            else if (sel == 2) w2 = corner;
            else               w3 = corner;
        }
        float wr = __shfl_down_sync(0xffffffffu, w0, 1);   // beta_next[u0+4]

        float4 cbl, cla;
        if (dtar > dm) {
            cbl = *reinterpret_cast<const float4*>(s_bl + (dtar - 1) * DSTR + uoff);
            cla = *reinterpret_cast<const float4*>(s_la + (dtar - 1) * DSTR + uoff);
        }
        for (int d = dtar - 1; d >= dm; --d) {
            int dn = max(d - 1, 0);                 // clamped prefetch
            float4 nbl = *reinterpret_cast<const float4*>(s_bl + dn * DSTR + uoff);
            float4 nla = *reinterpret_cast<const float4*>(s_la + dn * DSTR + uoff);

            float nb0 = dstep(w0, w1, cbl.x, cla.x);
            float nwr = __shfl_down_sync(0xffffffffu, nb0, 1);  // early, off-chain
            float nb1 = dstep(w1, w2, cbl.y, cla.y);
            float nb2 = dstep(w2, w3, cbl.z, cla.z);
            float nb3 = dstep(w3, wr, cbl.w, cla.w);

            w0 = nb0; w1 = nb1; w2 = nb2; w3 = nb3; wr = nwr;
            cbl = nbl; cla = nla;
        }
        *reinterpret_cast<float4*>(s_cmb + uoff) = make_float4(w0, w1, w2, w3);
        asm volatile("bar.sync 1, 64;" ::: "memory");
        return;
    }

    // ---------------- FORWARD alpha: diag 1 up to dm -------------------------
    float v0 = NEG_INF, v1 = NEG_INF, v2 = NEG_INF, v3 = NEG_INF;
    if (lane == 0) v0 = 0.0f;                      // alpha[0][0] (log2 domain)

    float4 cbl = *reinterpret_cast<const float4*>(s_bl + uoff);   // source row 0
    float4 cla = *reinterpret_cast<const float4*>(s_la + uoff);
    float vleft = NEG_INF;                                        // alpha[.][u0-1]
    float lleft = __shfl_up_sync(0xffffffffu, cla.w, 1);          // la[.][u0-1]

    for (int d = 1; d <= dm; ++d) {
        float4 nbl = *reinterpret_cast<const float4*>(s_bl + d * DSTR + uoff);
        float4 nla = *reinterpret_cast<const float4*>(s_la + d * DSTR + uoff);

        float nv3 = dstep(v3, v2, cbl.w, cla.z);   // first: feeds early shfl
        float nvl = __shfl_up_sync(0xffffffffu, nv3, 1);
        float nv0 = dstep(v0, vleft, cbl.x, lleft);
        float nv1 = dstep(v1, v0,    cbl.y, cla.x);
        float nv2 = dstep(v2, v1,    cbl.z, cla.y);
        float nll = __shfl_up_sync(0xffffffffu, nla.w, 1);

        vleft = (lane == 0) ? NEG_INF : nvl;
        lleft = nll;
        v0 = nv0; v1 = nv1; v2 = nv2; v3 = nv3;
        cbl = nbl; cla = nla;
    }

    asm volatile("bar.sync 1, 64;" ::: "memory");

    // ---------------- Combine at the cut: LSE over valid u -------------------
    float4 bt = *reinterpret_cast<const float4*>(s_cmb + uoff);
    int lo = max(0, dm - (tl - 1));
    int hi = min(dm, ul);
    float t0 = (u0     >= lo && u0     <= hi) ? v0 + bt.x : NEG_INF;
    float t1 = (u0 + 1 >= lo && u0 + 1 <= hi) ? v1 + bt.y : NEG_INF;
    float t2 = (u0 + 2 >= lo && u0 + 2 <= hi) ? v2 + bt.z : NEG_INF;
    float t3 = (u0 + 3 >= lo && u0 + 3 <= hi) ? v3 + bt.w : NEG_INF;

    float m = fmaxf(fmaxf(t0, t1), fmaxf(t2, t3));
#pragma unroll
    for (int o = 16; o; o >>= 1) m = fmaxf(m, __shfl_xor_sync(0xffffffffu, m, o));

    float e0, e1, e2, e3;
    asm("ex2.approx.f32 %0, %1;" : "=f"(e0) : "f"(t0 - m));
    asm("ex2.approx.f32 %0, %1;" : "=f"(e1) : "f"(t1 - m));
    asm("ex2.approx.f32 %0, %1;" : "=f"(e2) : "f"(t2 - m));
    asm("ex2.approx.f32 %0, %1;" : "=f"(e3) : "f"(t3 - m));
    float s = (e0 + e1) + (e2 + e3);
#pragma unroll
    for (int o = 16; o; o >>= 1) s += __shfl_xor_sync(0xffffffffu, s, o);

    if (lane == 0) {
        float l;  asm("lg2.approx.f32 %0, %1;" : "=f"(l) : "f"(s));
        g_ll[b] = m + l;                          // log2-domain log-likelihood
        __threadfence();
        int prev = atomicAdd(&g_done, 1);
        if (prev == Bb - 1) {                     // deterministic final reduce
            __threadfence();
            float sll = 0.0f;
#pragma unroll
            for (int i = 0; i < Bb; ++i) sll += __ldcg(&g_ll[i]);
            out[0] = sll * (-LN2 / (float)Bb);
            g_done = 0;                           // reset for next graph replay
        }
    }
}

extern "C" void kernel_launch(void* const* d_in, const int* in_sizes, int n_in,
                              void* d_out, int out_size) {
    const float* logits  = (const float*)d_in[0];
    const int*   targets = (const int*)d_in[1];
    const int*   tl      = (const int*)d_in[2];
    const int*   ul      = (const int*)d_in[3];

    const int ROWS = Bb * Tt * U1;                 // 207360 rows, 8 warps/block
    lse_kernel<<<ROWS / 8, 256>>>(logits, targets, tl, ul);

    size_t smem = (2 * NDIAG * DSTR + 128) * sizeof(float);  // tables + cut buf
    cudaFuncSetAttribute(dp_kernel, cudaFuncAttributeMaxDynamicSharedMemorySize, (int)smem);
    dp_kernel<<<Bb, 128, smem>>>(tl, ul, (float*)d_out);
}

// round 8
// speedup vs baseline: 2.1580x; 1.1366x over previous
#include <cuda_runtime.h>

#define Bb 16
#define Tt 160
#define Uu 80
#define U1 81
#define Vv 512
#define NDIAG 240     // diagonals d = t+u in [0,239]
#define DSTR 88       // diagonal row stride (floats), 16B aligned
#define L2E 1.4426950408889634f
#define LN2 0.6931471805599453f
#define NEG_INF __int_as_float(0xFF800000)
#define PADB Bb       // pad-fill blocks prepended to lse grid

// Scratch (allocation-free rule). Tables: log2-domain, anti-diagonal layout.
// Every cell of rows [0,239] is written each launch: live rows get data,
// dead rows get -inf (lane 0 of their warp), geometry pads get -inf (pad blocks).
__device__ float g_blank[Bb*NDIAG*DSTR];
__device__ float g_lab  [Bb*NDIAG*DSTR];
__device__ float g_ll   [Bb];
__device__ int   g_done;              // dp completion counter; self-resetting

// ---------------------------------------------------------------------------
__device__ __forceinline__ float exp_fast(float x) {   // FMA-only
    const float MAGIC = 12582912.0f;                    // 1.5 * 2^23
    float z = fmaf(x, L2E, MAGIC);
    float w = z - MAGIC;
    float f = fmaf(x, L2E, -w);
    float p =               9.6181291076e-3f;
    p = fmaf(p, f, 5.5504108664e-2f);
    p = fmaf(p, f, 2.4022650696e-1f);
    p = fmaf(p, f, 6.9314718056e-1f);
    p = fmaf(p, f, 1.0f);
    return __int_as_float(__float_as_int(p) + (__float_as_int(z) << 23));
}

// log2-domain logaddexp of (vs+bl, vl+la). NaN from (-inf)-(-inf) clamped.
__device__ __forceinline__ float dstep(float vs, float vl, float bl, float la) {
    float x = vs + bl;
    float y = vl + la;
    float mx = fmaxf(x, y);
    float mn = fminf(x, y);
    float nd = fmaxf(mn - mx, -126.0f);
    float e;  asm("ex2.approx.f32 %0, %1;" : "=f"(e) : "f"(nd));
    float l;  asm("lg2.approx.f32 %0, %1;" : "=f"(l) : "f"(1.0f + e));
    return mx + l;
}

__device__ __forceinline__ void cp16(unsigned int s, const void* g) {
    asm volatile("cp.async.cg.shared.global [%0], [%1], 16;" :: "r"(s), "l"(g));
}

// ---------------------------------------------------------------------------
// Kernel 1: blocks [0,PADB): geometry pad fill. Blocks >= PADB: per-row
// logsumexp over V=512 (dead rows write -inf and skip all logit traffic).
// ---------------------------------------------------------------------------
__global__ void __launch_bounds__(256) lse_kernel(const float* __restrict__ logits,
                                                  const int* __restrict__ targets,
                                                  const int* __restrict__ tl_arr,
                                                  const int* __restrict__ ul_arr) {
    if (blockIdx.x < PADB) {
        int b = blockIdx.x;
        float* bbl = g_blank + b * NDIAG * DSTR;
        float* bla = g_lab   + b * NDIAG * DSTR;
        for (int idx = threadIdx.x; idx < NDIAG * DSTR; idx += 256) {
            int d = idx / DSTR;               // const divide -> mul/shift
            int u = idx - d * DSTR;
            int lo = max(0, d - 159), hi = min(d, 80);
            if (u < lo || u > hi) { bbl[idx] = NEG_INF; bla[idx] = NEG_INF; }
        }
        return;
    }

    int gw   = ((blockIdx.x - PADB) * 256 + threadIdx.x) >> 5;  // row id
    int lane = threadIdx.x & 31;

    int u  = gw % U1;
    int bt = gw / U1;
    int t  = bt % Tt;
    int b  = bt / Tt;
    int o  = (b * NDIAG + (t + u)) * DSTR + u;
    if (t >= __ldg(tl_arr + b) || u > __ldg(ul_arr + b)) {  // dead row: -inf cell
        if (lane == 0) { g_blank[o] = NEG_INF; g_lab[o] = NEG_INF; }
        return;
    }

    const float4* p = reinterpret_cast<const float4*>(logits) + (size_t)gw * (Vv / 4);
    float4 a  = __ldcs(p + lane);
    float4 b4 = __ldcs(p + lane + 32);
    float4 c  = __ldcs(p + lane + 64);
    float4 dd = __ldcs(p + lane + 96);

    float s0 = (exp_fast(a.x)  + exp_fast(a.y))  + (exp_fast(a.z)  + exp_fast(a.w));
    float s1 = (exp_fast(b4.x) + exp_fast(b4.y)) + (exp_fast(b4.z) + exp_fast(b4.w));
    float s2 = (exp_fast(c.x)  + exp_fast(c.y))  + (exp_fast(c.z)  + exp_fast(c.w));
    float s3 = (exp_fast(dd.x) + exp_fast(dd.y)) + (exp_fast(dd.z) + exp_fast(dd.w));
    float s  = (s0 + s1) + (s2 + s3);
#pragma unroll
    for (int o2 = 16; o2; o2 >>= 1) s += __shfl_xor_sync(0xffffffffu, s, o2);

    float blank_logit = __shfl_sync(0xffffffffu, dd.w, 31);  // element 511

    if (lane == 0) {
        float lse2;
        asm("lg2.approx.f32 %0, %1;" : "=f"(lse2) : "f"(s));
        int tgt = targets[b * Uu + min(u, Uu - 1)];
        float lab_logit = __ldg(logits + (size_t)gw * Vv + tgt);
        g_blank[o] = fmaf(blank_logit, L2E, -lse2);
        g_lab[o]   = fmaf(lab_logit,   L2E, -lse2);
    }
}

// ---------------------------------------------------------------------------
// Kernel 2: meet-in-the-middle DP, one 64-thread block per batch.
// cp.async preload (tables arrive fully padded), then:
//   warp 0: forward alpha to cut dm; warp 1: backward beta to dm;
//   combine: log_like = LSE_u(alpha[dm][u] + beta[dm][u]).
// ---------------------------------------------------------------------------
__global__ void __launch_bounds__(64) dp_kernel(const int* __restrict__ tl_arr,
                                                const int* __restrict__ ul_arr,
                                                float* __restrict__ out) {
    extern __shared__ float sm[];
    float* s_bl  = sm;
    float* s_la  = sm + NDIAG * DSTR;
    float* s_cmb = sm + 2 * NDIAG * DSTR;  // 88 floats: beta on the cut
    int b = blockIdx.x;

    int tl = __ldg(tl_arr + b), ul = __ldg(ul_arr + b);
    int dtar = tl - 1 + ul;
    int dm   = dtar >> 1;

    // Async preload rows [0, dtar] of both tables (pads included).
    int n4 = (dtar + 1) * (DSTR / 4);
    const float4* gb = reinterpret_cast<const float4*>(g_blank + b * NDIAG * DSTR);
    const float4* gl = reinterpret_cast<const float4*>(g_lab   + b * NDIAG * DSTR);
    unsigned int sb = (unsigned int)__cvta_generic_to_shared(s_bl);
    unsigned int sl = (unsigned int)__cvta_generic_to_shared(s_la);
    for (int i = threadIdx.x; i < n4; i += 64) {
        cp16(sb + 16u * i, gb + i);
        cp16(sl + 16u * i, gl + i);
    }
    asm volatile("cp.async.commit_group;");
    asm volatile("cp.async.wait_group 0;");
    __syncthreads();

    int wid  = threadIdx.x >> 5;
    int lane = threadIdx.x & 31;
    int u0   = lane * 4;
    int uoff = min(u0, 84);

    if (wid == 1) {
        // ---------------- BACKWARD beta: diag dtar-1 down to dm -------------
        float w0 = NEG_INF, w1 = NEG_INF, w2 = NEG_INF, w3 = NEG_INF;
        float corner = s_bl[dtar * DSTR + ul];     // beta[tl-1][ul] = blank there
        if (lane == (ul >> 2)) {
            int sel = ul & 3;
            if      (sel == 0) w0 = corner;
            else if (sel == 1) w1 = corner;
            else if (sel == 2) w2 = corner;
            else               w3 = corner;
        }
        float wr = __shfl_down_sync(0xffffffffu, w0, 1);   // beta_next[u0+4]

        float4 cbl, cla;
        if (dtar > dm) {
            cbl = *reinterpret_cast<const float4*>(s_bl + (dtar - 1) * DSTR + uoff);
            cla = *reinterpret_cast<const float4*>(s_la + (dtar - 1) * DSTR + uoff);
        }
        for (int d = dtar - 1; d >= dm; --d) {
            int dn = max(d - 1, 0);                 // clamped prefetch
            float4 nbl = *reinterpret_cast<const float4*>(s_bl + dn * DSTR + uoff);
            float4 nla = *reinterpret_cast<const float4*>(s_la + dn * DSTR + uoff);

            float nb0 = dstep(w0, w1, cbl.x, cla.x);
            float nwr = __shfl_down_sync(0xffffffffu, nb0, 1);  // early, off-chain
            float nb1 = dstep(w1, w2, cbl.y, cla.y);
            float nb2 = dstep(w2, w3, cbl.z, cla.z);
            float nb3 = dstep(w3, wr, cbl.w, cla.w);

            w0 = nb0; w1 = nb1; w2 = nb2; w3 = nb3; wr = nwr;
            cbl = nbl; cla = nla;
        }
        *reinterpret_cast<float4*>(s_cmb + uoff) = make_float4(w0, w1, w2, w3);
        asm volatile("bar.sync 1, 64;" ::: "memory");
        return;
    }

    // ---------------- FORWARD alpha: diag 1 up to dm -------------------------
    float v0 = NEG_INF, v1 = NEG_INF, v2 = NEG_INF, v3 = NEG_INF;
    if (lane == 0) v0 = 0.0f;                      // alpha[0][0] (log2 domain)

    float4 cbl = *reinterpret_cast<const float4*>(s_bl + uoff);   // source row 0
    float4 cla = *reinterpret_cast<const float4*>(s_la + uoff);
    float vleft = NEG_INF;                                        // alpha[.][u0-1]
    float lleft = __shfl_up_sync(0xffffffffu, cla.w, 1);          // la[.][u0-1]

    for (int d = 1; d <= dm; ++d) {
        float4 nbl = *reinterpret_cast<const float4*>(s_bl + d * DSTR + uoff);
        float4 nla = *reinterpret_cast<const float4*>(s_la + d * DSTR + uoff);

        float nv3 = dstep(v3, v2, cbl.w, cla.z);   // first: feeds early shfl
        float nvl = __shfl_up_sync(0xffffffffu, nv3, 1);
        float nv0 = dstep(v0, vleft, cbl.x, lleft);
        float nv1 = dstep(v1, v0,    cbl.y, cla.x);
        float nv2 = dstep(v2, v1,    cbl.z, cla.y);
        float nll = __shfl_up_sync(0xffffffffu, nla.w, 1);

        vleft = (lane == 0) ? NEG_INF : nvl;
        lleft = nll;
        v0 = nv0; v1 = nv1; v2 = nv2; v3 = nv3;
        cbl = nbl; cla = nla;
    }

    asm volatile("bar.sync 1, 64;" ::: "memory");

    // ---------------- Combine at the cut: LSE over valid u -------------------
    float4 bt = *reinterpret_cast<const float4*>(s_cmb + uoff);
    int lo = max(0, dm - (tl - 1));
    int hi = min(dm, ul);
    float t0 = (u0     >= lo && u0     <= hi) ? v0 + bt.x : NEG_INF;
    float t1 = (u0 + 1 >= lo && u0 + 1 <= hi) ? v1 + bt.y : NEG_INF;
    float t2 = (u0 + 2 >= lo && u0 + 2 <= hi) ? v2 + bt.z : NEG_INF;
    float t3 = (u0 + 3 >= lo && u0 + 3 <= hi) ? v3 + bt.w : NEG_INF;

    float m = fmaxf(fmaxf(t0, t1), fmaxf(t2, t3));
#pragma unroll
    for (int o = 16; o; o >>= 1) m = fmaxf(m, __shfl_xor_sync(0xffffffffu, m, o));

    float e0, e1, e2, e3;
    asm("ex2.approx.f32 %0, %1;" : "=f"(e0) : "f"(t0 - m));
    asm("ex2.approx.f32 %0, %1;" : "=f"(e1) : "f"(t1 - m));
    asm("ex2.approx.f32 %0, %1;" : "=f"(e2) : "f"(t2 - m));
    asm("ex2.approx.f32 %0, %1;" : "=f"(e3) : "f"(t3 - m));
    float s = (e0 + e1) + (e2 + e3);
#pragma unroll
    for (int o = 16; o; o >>= 1) s += __shfl_xor_sync(0xffffffffu, s, o);

    if (lane == 0) {
        float l;  asm("lg2.approx.f32 %0, %1;" : "=f"(l) : "f"(s));
        g_ll[b] = m + l;                          // log2-domain log-likelihood
        __threadfence();
        int prev = atomicAdd(&g_done, 1);
        if (prev == Bb - 1) {                     // deterministic final reduce
            __threadfence();
            float sll = 0.0f;
#pragma unroll
            for (int i = 0; i < Bb; ++i) sll += __ldcg(&g_ll[i]);
            out[0] = sll * (-LN2 / (float)Bb);
            g_done = 0;                           // reset for next graph replay
        }
    }
}

extern "C" void kernel_launch(void* const* d_in, const int* in_sizes, int n_in,
                              void* d_out, int out_size) {
    const float* logits  = (const float*)d_in[0];
    const int*   targets = (const int*)d_in[1];
    const int*   tl      = (const int*)d_in[2];
    const int*   ul      = (const int*)d_in[3];

    const int ROWS = Bb * Tt * U1;                 // 207360 rows, 8 warps/block
    lse_kernel<<<PADB + ROWS / 8, 256>>>(logits, targets, tl, ul);

    size_t smem = (2 * NDIAG * DSTR + 128) * sizeof(float);  // tables + cut buf
    cudaFuncSetAttribute(dp_kernel, cudaFuncAttributeMaxDynamicSharedMemorySize, (int)smem);
    dp_kernel<<<Bb, 64, smem>>>(tl, ul, (float*)d_out);
}